// round 8
// baseline (speedup 1.0000x reference)
#include <cuda_runtime.h>
#include <cuda_fp16.h>
#include <math.h>

#define W 512
#define H 512
#define BATCH 16
#define NPIX (W*H)
#define NMAP (BATCH*NPIX)
#define EPSF 1e-4f
#define NT 512

#define NANF __int_as_float(0x7fffffff)

__device__ float g_gray[2 * NMAP];
__device__ double g_acc;

// ---------------- smem layout (4-byte units; half2 = 1 unit) ----------------
// gray : 58x58 s60 fp32 -> 3480 @0
// sga2 : 56x56 s56 half2(ga,-ga) -> 3136 @3480   NaN outside
// go2  : 44x44 s44 half2(go,-go) -> 1936 @6616   NaN outside
// A 4416 @8552 : sg0 48x48 s48 fp32 (2304) + hs5 48x44 s44 fp32 (2112 @A+2304)
//                then h72 44x38 s40 half2 (1760 @A)
//                then h7sa 38x32 fp32 (1216 @A) + h7sb (1216 @A+1216)
// B 3072 @12968: hm2 56x48 half2 (2688 @B)
//                then h17a 48x32 fp32 (1536 @B) + h17b (1536 @B+1536)
// C 2304 @16040: pm2 48x48 half2 (2304 @C)
//                then m72 38x38 s40 half2 (1520 @C)
#define OFF_GRAY 0
#define OFF_SGA  3480
#define OFF_GO   6616
#define OFF_A    8552
#define OFF_B    12968
#define OFF_C    16040
#define SMEM_FLOATS 18344
#define SMEM_BYTES (SMEM_FLOATS * 4)

struct __align__(16) H2x4 { __half2 v[4]; };

__global__ void k_zero() { g_acc = 0.0; }

__global__ void k_gray(const float* __restrict__ in, float* __restrict__ outp) {
    int i = blockIdx.x * blockDim.x + threadIdx.x;
    if (i >= NMAP / 4) return;
    int b = i / (NPIX / 4);
    int p = i - b * (NPIX / 4);
    const float4* base = (const float4*)(in + (size_t)b * 3 * NPIX);
    float4 r = base[p];
    float4 g = base[NPIX / 4 + p];
    float4 bl = base[2 * (NPIX / 4) + p];
    float4 o;
    o.x = 0.299f * r.x + 0.587f * g.x + 0.114f * bl.x;
    o.y = 0.299f * r.y + 0.587f * g.y + 0.114f * bl.y;
    o.z = 0.299f * r.z + 0.587f * g.z + 0.114f * bl.z;
    o.w = 0.299f * r.w + 0.587f * g.w + 0.114f * bl.w;
    ((float4*)outp)[i] = o;
}

__global__ __launch_bounds__(NT, 2)
void k_mega() {
    extern __shared__ float S[];
    __half2* S2 = reinterpret_cast<__half2*>(S);
    __shared__ double sred[NT / 32];

    const int b = blockIdx.z;
    const int X0 = blockIdx.x * 32, Y0 = blockIdx.y * 32;
    const int tid = threadIdx.x;

    const __half2 nan2 = __floats2half2_rn(NANF, NANF);
    const __half2 zero2 = __float2half2_rn(0.f);

    double acc = 0.0;
    float vsave[2][4];
    float gmv[4], gnv[4];   // gmax1 and (-gmin1), registers for tid<256

    #pragma unroll
    for (int img = 0; img < 2; ++img) {
        const float* __restrict__ gp = g_gray + (size_t)img * NMAP + (size_t)b * NPIX;

        __syncthreads();
        for (int idx = tid; idx < 3364; idx += NT) {
            int r = idx / 58, c = idx - r * 58;
            int gy = Y0 - 12 + r, gx = X0 - 12 + c;
            float v = 0.f;
            if ((unsigned)gx < (unsigned)W && (unsigned)gy < (unsigned)H)
                v = __ldg(gp + gy * W + gx);
            S[OFF_GRAY + r * 60 + c] = v;
        }
        __syncthreads();

        #pragma unroll
        for (int dir = 0; dir < 2; ++dir) {
            // ======== P1: sga2 (56x56 half2, NaN outside) ; sg0 (48x48 fp32, 0 outside) ========
            #pragma unroll
            for (int idx = tid; idx < 784; idx += NT) {
                int r = idx / 14, g4 = (idx - r * 14) * 4;
                const float* p = S + OFF_GRAY + r * 60 + g4;
                float4 a = *(const float4*)p;
                float n0, n1, n2, n3;
                if (dir == 0) {
                    float e = p[4];
                    n0 = a.y; n1 = a.z; n2 = a.w; n3 = e;
                } else {
                    float4 bb = *(const float4*)(p + 60);
                    n0 = bb.x; n1 = bb.y; n2 = bb.z; n3 = bb.w;
                }
                int gy = Y0 - 12 + r, gxb = X0 - 12 + g4;
                bool iny = (unsigned)gy < (unsigned)H;
                float d0 = fabsf(a.x - n0), d1 = fabsf(a.y - n1);
                float d2 = fabsf(a.z - n2), d3 = fabsf(a.w - n3);
                H2x4 o;
                o.v[0] = (iny && (unsigned)(gxb + 0) < (unsigned)W) ? __floats2half2_rn(d0, -d0) : nan2;
                o.v[1] = (iny && (unsigned)(gxb + 1) < (unsigned)W) ? __floats2half2_rn(d1, -d1) : nan2;
                o.v[2] = (iny && (unsigned)(gxb + 2) < (unsigned)W) ? __floats2half2_rn(d2, -d2) : nan2;
                o.v[3] = (iny && (unsigned)(gxb + 3) < (unsigned)W) ? __floats2half2_rn(d3, -d3) : nan2;
                *(H2x4*)(S2 + OFF_SGA + r * 56 + g4) = o;
            }
            #pragma unroll
            for (int idx = tid; idx < 576; idx += NT) {
                int r = idx / 12, g4 = (idx - r * 12) * 4;
                const float* p = S + OFF_GRAY + (r + 4) * 60 + g4 + 4;
                float4 a = *(const float4*)p;
                float n0, n1, n2, n3;
                if (dir == 0) {
                    float e = p[4];
                    n0 = a.y; n1 = a.z; n2 = a.w; n3 = e;
                } else {
                    float4 bb = *(const float4*)(p + 60);
                    n0 = bb.x; n1 = bb.y; n2 = bb.z; n3 = bb.w;
                }
                int gy = Y0 - 8 + r, gxb = X0 - 8 + g4;
                bool iny = (unsigned)gy < (unsigned)H;
                float4 o;
                o.x = (iny && (unsigned)(gxb + 0) < (unsigned)W) ? (a.x - n0) : 0.f;
                o.y = (iny && (unsigned)(gxb + 1) < (unsigned)W) ? (a.y - n1) : 0.f;
                o.z = (iny && (unsigned)(gxb + 2) < (unsigned)W) ? (a.z - n2) : 0.f;
                o.w = (iny && (unsigned)(gxb + 3) < (unsigned)W) ? (a.w - n3) : 0.f;
                *(float4*)(S + OFF_A + r * 48 + g4) = o;
            }
            __syncthreads();

            // ======== P2: hm2 (56x48) 9-tap h max/min via hmax2 ; hs5 (48x44) fp32 ========
            #pragma unroll
            for (int idx = tid; idx < 672; idx += NT) {
                int r = idx / 12, g4 = (idx - r * 12) * 4;
                const __half2* p = S2 + OFF_SGA + r * 56 + g4;
                H2x4 A = *(const H2x4*)p;
                H2x4 Bv = *(const H2x4*)(p + 4);
                H2x4 Cv = *(const H2x4*)(p + 8);
                __half2 t0=A.v[0],t1=A.v[1],t2=A.v[2],t3=A.v[3];
                __half2 t4=Bv.v[0],t5=Bv.v[1],t6=Bv.v[2],t7=Bv.v[3];
                __half2 t8=Cv.v[0],t9=Cv.v[1],t10=Cv.v[2],t11=Cv.v[3];
                __half2 core = __hmax2(__hmax2(__hmax2(t3,t4),__hmax2(t5,t6)),__hmax2(t7,t8));
                __half2 t12 = __hmax2(t1,t2);
                H2x4 o;
                o.v[0] = __hmax2(__hmax2(core,t0), t12);
                o.v[1] = __hmax2(__hmax2(core,t9), t12);
                o.v[2] = __hmax2(__hmax2(core,t2), __hmax2(t9,t10));
                o.v[3] = __hmax2(core, __hmax2(t9,__hmax2(t10,t11)));
                *(H2x4*)(S2 + OFF_B + r * 48 + g4) = o;
            }
            #pragma unroll
            for (int idx = tid; idx < 528; idx += NT) {
                int r = idx / 11, g4 = (idx - r * 11) * 4;
                const float* p = S + OFF_A + r * 48 + g4;
                float4 A = *(const float4*)p;
                float4 Bv = *(const float4*)(p + 4);
                float s0 = A.x + A.y + A.z + A.w + Bv.x;
                float s1 = s0 - A.x + Bv.y;
                float s2 = s1 - A.y + Bv.z;
                float s3 = s2 - A.z + Bv.w;
                *(float4*)(S + OFF_A + 2304 + r * 44 + g4) = make_float4(s0, s1, s2, s3);
            }
            __syncthreads();

            // ======== P3: pm2 (48x48 v 9-tap, masked 0 outside) ; go2 (44x44) ========
            #pragma unroll
            for (int idx = tid; idx < 576; idx += NT) {
                int rg = idx / 48, c = idx - rg * 48;
                int r4 = rg * 4;
                int gx = X0 - 8 + c;
                bool inx = (unsigned)gx < (unsigned)W;
                int gyb = Y0 - 8 + r4;
                __half2 t[12];
                #pragma unroll
                for (int q = 0; q < 12; ++q) t[q] = S2[OFF_B + (r4 + q) * 48 + c];
                __half2 core = __hmax2(__hmax2(__hmax2(t[3],t[4]),__hmax2(t[5],t[6])),__hmax2(t[7],t[8]));
                __half2 t12 = __hmax2(t[1],t[2]);
                __half2 o0 = __hmax2(__hmax2(core,t[0]), t12);
                __half2 o1 = __hmax2(__hmax2(core,t[9]), t12);
                __half2 o2 = __hmax2(__hmax2(core,t[2]), __hmax2(t[9],t[10]));
                __half2 o3 = __hmax2(core, __hmax2(t[9],__hmax2(t[10],t[11])));
                bool i0 = inx && (unsigned)(gyb + 0) < (unsigned)H;
                bool i1 = inx && (unsigned)(gyb + 1) < (unsigned)H;
                bool i2 = inx && (unsigned)(gyb + 2) < (unsigned)H;
                bool i3 = inx && (unsigned)(gyb + 3) < (unsigned)H;
                S2[OFF_C + (r4 + 0) * 48 + c] = i0 ? o0 : zero2;
                S2[OFF_C + (r4 + 1) * 48 + c] = i1 ? o1 : zero2;
                S2[OFF_C + (r4 + 2) * 48 + c] = i2 ? o2 : zero2;
                S2[OFF_C + (r4 + 3) * 48 + c] = i3 ? o3 : zero2;
            }
            #pragma unroll
            for (int idx = tid; idx < 484; idx += NT) {
                int rg = idx / 44, c = idx - rg * 44;
                int r4 = rg * 4;
                float t[8];
                #pragma unroll
                for (int q = 0; q < 8; ++q) t[q] = S[OFF_A + 2304 + (r4 + q) * 44 + c];
                float s0 = t[0] + t[1] + t[2] + t[3] + t[4];
                float s1 = s0 - t[0] + t[5];
                float s2 = s1 - t[1] + t[6];
                float s3 = s2 - t[2] + t[7];
                float ss[4] = { s0, s1, s2, s3 };
                int gx = X0 - 6 + c;
                float cntx = (float)(min(gx + 2, W - 1) - max(gx - 2, 0) + 1);
                #pragma unroll
                for (int j = 0; j < 4; ++j) {
                    int gy = Y0 - 6 + r4 + j;
                    __half2 ov = nan2;
                    if ((unsigned)gx < (unsigned)W && (unsigned)gy < (unsigned)H) {
                        float cnty = (float)(min(gy + 2, H - 1) - max(gy - 2, 0) + 1);
                        float v = fabsf(__fdividef(ss[j], cntx * cnty));
                        ov = __floats2half2_rn(v, -v);
                    }
                    S2[OFF_GO + (r4 + j) * 44 + c] = ov;
                }
            }
            __syncthreads();

            // ======== P4: h17 fp32 sums of pm2 (48x32) ; h72 (44x38) 7-tap h of go2 ========
            #pragma unroll
            for (int idx = tid; idx < 384; idx += NT) {
                int r = idx / 8, g4 = (idx & 7) * 4;
                const __half2* p = S2 + OFF_C + r * 48 + g4;
                float ta[20], tb[20];
                #pragma unroll
                for (int q = 0; q < 5; ++q) {
                    H2x4 v = *(const H2x4*)(p + q * 4);
                    #pragma unroll
                    for (int w = 0; w < 4; ++w) {
                        float2 f = __half22float2(v.v[w]);
                        ta[q*4+w] = f.x; tb[q*4+w] = f.y;
                    }
                }
                float a0 = 0.f, b0 = 0.f;
                #pragma unroll
                for (int q = 0; q < 17; ++q) { a0 += ta[q]; b0 += tb[q]; }
                float a1 = a0 - ta[0] + ta[17], b1 = b0 - tb[0] + tb[17];
                float a2 = a1 - ta[1] + ta[18], b2 = b1 - tb[1] + tb[18];
                float a3 = a2 - ta[2] + ta[19], b3 = b2 - tb[2] + tb[19];
                *(float4*)(S + OFF_B + r * 32 + g4) = make_float4(a0, a1, a2, a3);
                *(float4*)(S + OFF_B + 1536 + r * 32 + g4) = make_float4(b0, b1, b2, b3);
            }
            #pragma unroll
            for (int idx = tid; idx < 440; idx += NT) {
                int r = idx / 10, g = idx - r * 10;
                if (g < 9) {
                    int g4 = g * 4;
                    const __half2* p = S2 + OFF_GO + r * 44 + g4;
                    H2x4 A = *(const H2x4*)p;
                    H2x4 Bv = *(const H2x4*)(p + 4);
                    H2x4 Cv = *(const H2x4*)(p + 8);
                    __half2 t0=A.v[0],t1=A.v[1],t2=A.v[2],t3=A.v[3];
                    __half2 t4=Bv.v[0],t5=Bv.v[1],t6=Bv.v[2],t7=Bv.v[3];
                    __half2 t8=Cv.v[0],t9=Cv.v[1];
                    __half2 core = __hmax2(__hmax2(t3,t4),__hmax2(t5,t6));
                    __half2 t12 = __hmax2(t1,t2);
                    H2x4 o;
                    o.v[0] = __hmax2(__hmax2(core,t0), t12);
                    o.v[1] = __hmax2(__hmax2(core,t7), t12);
                    o.v[2] = __hmax2(__hmax2(core,t2), __hmax2(t7,t8));
                    o.v[3] = __hmax2(core, __hmax2(t7,__hmax2(t8,t9)));
                    *(H2x4*)(S2 + OFF_A + r * 40 + g4) = o;
                } else {
                    const __half2* p = S2 + OFF_GO + r * 44 + 36;
                    H2x4 A = *(const H2x4*)p;
                    H2x4 Bv = *(const H2x4*)(p + 4);
                    __half2 t0=A.v[0],t1=A.v[1],t2=A.v[2],t3=A.v[3];
                    __half2 t4=Bv.v[0],t5=Bv.v[1],t6=Bv.v[2],t7=Bv.v[3];
                    __half2 c6 = __hmax2(__hmax2(t1,t2),__hmax2(__hmax2(t3,t4),__hmax2(t5,t6)));
                    S2[OFF_A + r * 40 + 36] = __hmax2(c6, t0);
                    S2[OFF_A + r * 40 + 37] = __hmax2(c6, t7);
                }
            }
            __syncthreads();

            // ======== P5: m72 (38x38 v 7-tap, masked) ; v17 fp32 -> regs ========
            #pragma unroll
            for (int idx = tid; idx < 380; idx += NT) {
                int rg = idx / 38, c = idx - rg * 38;
                int r0 = min(rg * 4, 34);
                int gx = X0 - 3 + c;
                bool inx = (unsigned)gx < (unsigned)W;
                int gyb = Y0 - 3 + r0;
                __half2 t[10];
                #pragma unroll
                for (int q = 0; q < 10; ++q) t[q] = S2[OFF_A + (r0 + q) * 40 + c];
                __half2 core = __hmax2(__hmax2(t[3],t[4]),__hmax2(t[5],t[6]));
                __half2 t12 = __hmax2(t[1],t[2]);
                __half2 o0 = __hmax2(__hmax2(core,t[0]), t12);
                __half2 o1 = __hmax2(__hmax2(core,t[7]), t12);
                __half2 o2 = __hmax2(__hmax2(core,t[2]), __hmax2(t[7],t[8]));
                __half2 o3 = __hmax2(core, __hmax2(t[7],__hmax2(t[8],t[9])));
                bool i0 = inx && (unsigned)(gyb + 0) < (unsigned)H;
                bool i1 = inx && (unsigned)(gyb + 1) < (unsigned)H;
                bool i2 = inx && (unsigned)(gyb + 2) < (unsigned)H;
                bool i3 = inx && (unsigned)(gyb + 3) < (unsigned)H;
                S2[OFF_C + (r0 + 0) * 40 + c] = i0 ? o0 : zero2;
                S2[OFF_C + (r0 + 1) * 40 + c] = i1 ? o1 : zero2;
                S2[OFF_C + (r0 + 2) * 40 + c] = i2 ? o2 : zero2;
                S2[OFF_C + (r0 + 3) * 40 + c] = i3 ? o3 : zero2;
            }
            if (tid < 256) {
                int rg = tid >> 5, c = tid & 31;
                int r0 = rg * 4;
                int gx = X0 + c;
                float cntx = (float)(min(gx + 8, W - 1) - max(gx - 8, 0) + 1);
                float inv[4];
                #pragma unroll
                for (int j = 0; j < 4; ++j) {
                    int gy = Y0 + r0 + j;
                    float cnty = (float)(min(gy + 8, H - 1) - max(gy - 8, 0) + 1);
                    inv[j] = __fdividef(1.f, cntx * cnty);
                }
                {
                    float t[20];
                    #pragma unroll
                    for (int q = 0; q < 20; ++q) t[q] = S[OFF_B + (r0 + q) * 32 + c];
                    float s0 = 0.f;
                    #pragma unroll
                    for (int q = 0; q < 17; ++q) s0 += t[q];
                    float s1 = s0 - t[0] + t[17];
                    float s2 = s1 - t[1] + t[18];
                    float s3 = s2 - t[2] + t[19];
                    gmv[0] = s0 * inv[0]; gmv[1] = s1 * inv[1];
                    gmv[2] = s2 * inv[2]; gmv[3] = s3 * inv[3];
                }
                {
                    float t[20];
                    #pragma unroll
                    for (int q = 0; q < 20; ++q) t[q] = S[OFF_B + 1536 + (r0 + q) * 32 + c];
                    float s0 = 0.f;
                    #pragma unroll
                    for (int q = 0; q < 17; ++q) s0 += t[q];
                    float s1 = s0 - t[0] + t[17];
                    float s2 = s1 - t[1] + t[18];
                    float s3 = s2 - t[2] + t[19];
                    gnv[0] = s0 * inv[0]; gnv[1] = s1 * inv[1];
                    gnv[2] = s2 * inv[2]; gnv[3] = s3 * inv[3];
                }
            }
            __syncthreads();

            // ======== P6: h7s fp32 7-tap h-sums of m72 (38x32 each channel) ========
            #pragma unroll
            for (int idx = tid; idx < 304; idx += NT) {
                int r = idx / 8, g4 = (idx & 7) * 4;
                const __half2* p = S2 + OFF_C + r * 40 + g4;
                float ta[10], tb[10];
                #pragma unroll
                for (int q = 0; q < 3; ++q) {
                    H2x4 v = *(const H2x4*)(p + q * 4);
                    #pragma unroll
                    for (int w = 0; w < 4; ++w) {
                        int k = q * 4 + w;
                        if (k < 10) {
                            float2 f = __half22float2(v.v[w]);
                            ta[k] = f.x; tb[k] = f.y;
                        }
                    }
                }
                float a0 = ta[0]+ta[1]+ta[2]+ta[3]+ta[4]+ta[5]+ta[6];
                float a1 = a0 - ta[0] + ta[7];
                float a2 = a1 - ta[1] + ta[8];
                float a3 = a2 - ta[2] + ta[9];
                float b0 = tb[0]+tb[1]+tb[2]+tb[3]+tb[4]+tb[5]+tb[6];
                float b1 = b0 - tb[0] + tb[7];
                float b2 = b1 - tb[1] + tb[8];
                float b3 = b2 - tb[2] + tb[9];
                *(float4*)(S + OFF_A + r * 32 + g4) = make_float4(a0, a1, a2, a3);
                *(float4*)(S + OFF_A + 1216 + r * 32 + g4) = make_float4(b0, b1, b2, b3);
            }
            __syncthreads();

            // ======== P7: final (32x32), tid<256 ========
            if (tid < 256) {
                int rg = tid >> 5, c = tid & 31;
                int r0 = rg * 4;
                float sA[4], sD[4];
                {
                    float t[10];
                    #pragma unroll
                    for (int q = 0; q < 10; ++q) t[q] = S[OFF_A + (r0 + q) * 32 + c];
                    sA[0] = t[0]+t[1]+t[2]+t[3]+t[4]+t[5]+t[6];
                    sA[1] = sA[0] - t[0] + t[7];
                    sA[2] = sA[1] - t[1] + t[8];
                    sA[3] = sA[2] - t[2] + t[9];
                }
                {
                    float t[10];
                    #pragma unroll
                    for (int q = 0; q < 10; ++q) t[q] = S[OFF_A + 1216 + (r0 + q) * 32 + c];
                    sD[0] = t[0]+t[1]+t[2]+t[3]+t[4]+t[5]+t[6];
                    sD[1] = sD[0] - t[0] + t[7];
                    sD[2] = sD[1] - t[1] + t[8];
                    sD[3] = sD[2] - t[2] + t[9];
                }
                int gx = X0 + c;
                float cntx = (float)(min(gx + 3, W - 1) - max(gx - 3, 0) + 1);
                #pragma unroll
                for (int j = 0; j < 4; ++j) {
                    int gy = Y0 + r0 + j;
                    float cnty = (float)(min(gy + 3, H - 1) - max(gy - 3, 0) + 1);
                    float inv = __fdividef(1.f, cntx * cnty);
                    float pmax = sA[j] * inv;
                    float pmin = -(sD[j] * inv);          // channel B held negated values
                    float go = __low2float(S2[OFF_GO + (r0 + j + 6) * 44 + c + 6]);
                    float ga = __low2float(S2[OFF_SGA + (r0 + j + 12) * 56 + c + 12]);
                    float gmax = gmv[j];
                    float gmin = -gnv[j];                 // gnv = avg of negated mins
                    float gn = __fdividef(go - pmin, fabsf(pmax - pmin) + EPSF);
                    float gn1 = __fdividef(ga - gmin, fabsf(gmax - gmin) + EPSF);
                    float val = (gn + 0.01f) * gn1;
                    if (img == 0) {
                        vsave[dir][j] = val;
                    } else {
                        float rv = vsave[dir][j];
                        acc += (double)(rv * expf(-10.f * (rv + val)));
                    }
                }
            }
            __syncthreads();
        }
    }

    // ---- block reduction ----
    int tx = tid & 31, ty = tid >> 5;
    #pragma unroll
    for (int off = 16; off; off >>= 1) acc += __shfl_down_sync(0xffffffffu, acc, off);
    if (tx == 0) sred[ty] = acc;
    __syncthreads();
    if (ty == 0 && tx < NT / 32) {
        double w = sred[tx];
        #pragma unroll
        for (int off = (NT / 64); off; off >>= 1) w += __shfl_down_sync(0xffffffffu, w, off);
        if (tx == 0) atomicAdd(&g_acc, w);
    }
}

__global__ void k_out(float* __restrict__ out) {
    out[0] = (float)(g_acc / (double)NMAP);
}

extern "C" void kernel_launch(void* const* d_in, const int* in_sizes, int n_in,
                              void* d_out, int out_size) {
    const float* R_low = (const float*)d_in[0];
    const float* low = (const float*)d_in[1];
    float* out = (float*)d_out;

    cudaFuncSetAttribute(k_mega, cudaFuncAttributeMaxDynamicSharedMemorySize, SMEM_BYTES);

    float* grayR;
    cudaGetSymbolAddress((void**)&grayR, g_gray);
    float* grayL = grayR + NMAP;

    int gray_blocks = (NMAP / 4 + 255) / 256;

    k_zero<<<1, 1>>>();
    k_gray<<<gray_blocks, 256>>>(R_low, grayR);
    k_gray<<<gray_blocks, 256>>>(low, grayL);

    dim3 grd(16, 16, 16);
    k_mega<<<grd, NT, SMEM_BYTES>>>();

    k_out<<<1, 1>>>(out);
}

// round 9
// speedup vs baseline: 1.2684x; 1.2684x over previous
#include <cuda_runtime.h>
#include <math.h>

#define W 512
#define H 512
#define BATCH 16
#define NPIX (W*H)
#define NMAP (BATCH*NPIX)
#define EPSF 1e-4f
#define NT 512

#define NANF __int_as_float(0x7fffffff)

__device__ float g_gray[2 * NMAP];
__device__ double g_acc;

// smem layout identical to R7 (fp32), 91.8KB -> 2 CTAs/SM
#define OFF_GRAY 0
#define OFF_SGA  3480
#define OFF_GO   6616
#define OFF_A    8552
#define OFF_B    12968
#define OFF_C    18344
#define SMEM_FLOATS 22952
#define SMEM_BYTES (SMEM_FLOATS * 4)

__global__ void k_zero() { g_acc = 0.0; }

__global__ void k_gray(const float* __restrict__ in, float* __restrict__ outp) {
    int i = blockIdx.x * blockDim.x + threadIdx.x;
    if (i >= NMAP / 4) return;
    int b = i / (NPIX / 4);
    int p = i - b * (NPIX / 4);
    const float4* base = (const float4*)(in + (size_t)b * 3 * NPIX);
    float4 r = base[p];
    float4 g = base[NPIX / 4 + p];
    float4 bl = base[2 * (NPIX / 4) + p];
    float4 o;
    o.x = 0.299f * r.x + 0.587f * g.x + 0.114f * bl.x;
    o.y = 0.299f * r.y + 0.587f * g.y + 0.114f * bl.y;
    o.z = 0.299f * r.z + 0.587f * g.z + 0.114f * bl.z;
    o.w = 0.299f * r.w + 0.587f * g.w + 0.114f * bl.w;
    ((float4*)outp)[i] = o;
}

// 9-tap max/min over 8 outputs from 16 values (van Herk split at index 8)
#define VH9(t, out, OP) do { \
    float s7=t[7], s6=OP(t[6],s7), s5=OP(t[5],s6), s4=OP(t[4],s5); \
    float s3=OP(t[3],s4), s2=OP(t[2],s3), s1=OP(t[1],s2), s0=OP(t[0],s1); \
    float p0=t[8], p1=OP(p0,t[9]), p2=OP(p1,t[10]), p3=OP(p2,t[11]); \
    float p4=OP(p3,t[12]), p5=OP(p4,t[13]), p6=OP(p5,t[14]), p7=OP(p6,t[15]); \
    out[0]=OP(s0,p0); out[1]=OP(s1,p1); out[2]=OP(s2,p2); out[3]=OP(s3,p3); \
    out[4]=OP(s4,p4); out[5]=OP(s5,p5); out[6]=OP(s6,p6); out[7]=OP(s7,p7); \
} while(0)

// 7-tap max/min over 8 outputs from 14 values (split at index 7)
#define VH7(t, out, OP) do { \
    float s6=t[6], s5=OP(t[5],s6), s4=OP(t[4],s5), s3=OP(t[3],s4); \
    float s2=OP(t[2],s3), s1=OP(t[1],s2), s0=OP(t[0],s1); \
    float p0=t[7], p1=OP(p0,t[8]), p2=OP(p1,t[9]), p3=OP(p2,t[10]); \
    float p4=OP(p3,t[11]), p5=OP(p4,t[12]), p6=OP(p5,t[13]); \
    out[0]=s0; out[1]=OP(s1,p0); out[2]=OP(s2,p1); out[3]=OP(s3,p2); \
    out[4]=OP(s4,p3); out[5]=OP(s5,p4); out[6]=OP(s6,p5); out[7]=p6; \
} while(0)

__global__ __launch_bounds__(NT, 2)
void k_mega() {
    extern __shared__ float S[];
    __shared__ double sred[NT / 32];

    const int b = blockIdx.z;
    const int X0 = blockIdx.x * 32, Y0 = blockIdx.y * 32;
    const int tid = threadIdx.x;

    double acc = 0.0;
    float vsave[2][4];
    float gmv[4], gnv[4];

    #pragma unroll
    for (int img = 0; img < 2; ++img) {
        const float* __restrict__ gp = g_gray + (size_t)img * NMAP + (size_t)b * NPIX;

        __syncthreads();
        for (int idx = tid; idx < 3364; idx += NT) {
            int r = idx / 58, c = idx - r * 58;
            int gy = Y0 - 12 + r, gx = X0 - 12 + c;
            float v = 0.f;
            if ((unsigned)gx < (unsigned)W && (unsigned)gy < (unsigned)H)
                v = __ldg(gp + gy * W + gx);
            S[OFF_GRAY + r * 60 + c] = v;
        }
        __syncthreads();

        #pragma unroll
        for (int dir = 0; dir < 2; ++dir) {
            // ======== P1: sga (56x56, NaN outside) + sg0 (48x48, 0 outside) ========
            for (int idx = tid; idx < 1360; idx += NT) {
                if (idx < 784) {
                    int r = idx / 14, g4 = (idx - r * 14) * 4;
                    const float* p = S + OFF_GRAY + r * 60 + g4;
                    float4 a = *(const float4*)p;
                    float n0, n1, n2, n3;
                    if (dir == 0) {
                        float e = p[4];
                        n0 = a.y; n1 = a.z; n2 = a.w; n3 = e;
                    } else {
                        float4 bb = *(const float4*)(p + 60);
                        n0 = bb.x; n1 = bb.y; n2 = bb.z; n3 = bb.w;
                    }
                    int gy = Y0 - 12 + r, gxb = X0 - 12 + g4;
                    bool iny = (unsigned)gy < (unsigned)H;
                    float4 o;
                    o.x = (iny && (unsigned)(gxb + 0) < (unsigned)W) ? fabsf(a.x - n0) : NANF;
                    o.y = (iny && (unsigned)(gxb + 1) < (unsigned)W) ? fabsf(a.y - n1) : NANF;
                    o.z = (iny && (unsigned)(gxb + 2) < (unsigned)W) ? fabsf(a.z - n2) : NANF;
                    o.w = (iny && (unsigned)(gxb + 3) < (unsigned)W) ? fabsf(a.w - n3) : NANF;
                    *(float4*)(S + OFF_SGA + r * 56 + g4) = o;
                } else {
                    int k = idx - 784;
                    int r = k / 12, g4 = (k - r * 12) * 4;
                    const float* p = S + OFF_GRAY + (r + 4) * 60 + g4 + 4;
                    float4 a = *(const float4*)p;
                    float n0, n1, n2, n3;
                    if (dir == 0) {
                        float e = p[4];
                        n0 = a.y; n1 = a.z; n2 = a.w; n3 = e;
                    } else {
                        float4 bb = *(const float4*)(p + 60);
                        n0 = bb.x; n1 = bb.y; n2 = bb.z; n3 = bb.w;
                    }
                    int gy = Y0 - 8 + r, gxb = X0 - 8 + g4;
                    bool iny = (unsigned)gy < (unsigned)H;
                    float4 o;
                    o.x = (iny && (unsigned)(gxb + 0) < (unsigned)W) ? (a.x - n0) : 0.f;
                    o.y = (iny && (unsigned)(gxb + 1) < (unsigned)W) ? (a.y - n1) : 0.f;
                    o.z = (iny && (unsigned)(gxb + 2) < (unsigned)W) ? (a.z - n2) : 0.f;
                    o.w = (iny && (unsigned)(gxb + 3) < (unsigned)W) ? (a.w - n3) : 0.f;
                    *(float4*)(S + OFF_A + r * 48 + g4) = o;
                }
            }
            __syncthreads();

            // ======== P2: hm 8-col vH (56x48) + hs5 (48x44) ========
            for (int idx = tid; idx < 864; idx += NT) {
                if (idx < 336) {
                    int r = idx / 6, g8 = (idx - r * 6) * 8;
                    const float* p = S + OFF_SGA + r * 56 + g8;
                    float t[16];
                    #pragma unroll
                    for (int q = 0; q < 4; ++q) {
                        float4 v = *(const float4*)(p + q * 4);
                        t[q*4] = v.x; t[q*4+1] = v.y; t[q*4+2] = v.z; t[q*4+3] = v.w;
                    }
                    float ox[8], on[8];
                    VH9(t, ox, fmaxf);
                    VH9(t, on, fminf);
                    float* bx = S + OFF_B + r * 48 + g8;
                    float* bn = S + OFF_B + 2688 + r * 48 + g8;
                    *(float4*)bx       = make_float4(ox[0], ox[1], ox[2], ox[3]);
                    *(float4*)(bx + 4) = make_float4(ox[4], ox[5], ox[6], ox[7]);
                    *(float4*)bn       = make_float4(on[0], on[1], on[2], on[3]);
                    *(float4*)(bn + 4) = make_float4(on[4], on[5], on[6], on[7]);
                } else {
                    int k = idx - 336;
                    int r = k / 11, g4 = (k - r * 11) * 4;
                    const float* p = S + OFF_A + r * 48 + g4;
                    float4 A = *(const float4*)p;
                    float4 Bv = *(const float4*)(p + 4);
                    float s0 = A.x + A.y + A.z + A.w + Bv.x;
                    float s1 = s0 - A.x + Bv.y;
                    float s2 = s1 - A.y + Bv.z;
                    float s3 = s2 - A.z + Bv.w;
                    *(float4*)(S + OFF_A + 2304 + r * 44 + g4) = make_float4(s0, s1, s2, s3);
                }
            }
            __syncthreads();

            // ======== P3: pm 8-row vH (48x48, masked 0 outside) + go 8-row (44x44) ========
            for (int idx = tid; idx < 552; idx += NT) {
                if (idx < 288) {
                    int rg = idx / 48, c = idx - rg * 48;
                    int r8 = rg * 8;
                    int gx = X0 - 8 + c;
                    bool inx = (unsigned)gx < (unsigned)W;
                    {
                        float t[16];
                        #pragma unroll
                        for (int q = 0; q < 16; ++q) t[q] = S[OFF_B + (r8 + q) * 48 + c];
                        float o[8];
                        VH9(t, o, fmaxf);
                        #pragma unroll
                        for (int j = 0; j < 8; ++j) {
                            int gy = Y0 - 8 + r8 + j;
                            bool in = inx && (unsigned)gy < (unsigned)H;
                            S[OFF_C + (r8 + j) * 48 + c] = in ? o[j] : 0.f;
                        }
                    }
                    {
                        float t[16];
                        #pragma unroll
                        for (int q = 0; q < 16; ++q) t[q] = S[OFF_B + 2688 + (r8 + q) * 48 + c];
                        float o[8];
                        VH9(t, o, fminf);
                        #pragma unroll
                        for (int j = 0; j < 8; ++j) {
                            int gy = Y0 - 8 + r8 + j;
                            bool in = inx && (unsigned)gy < (unsigned)H;
                            S[OFF_C + 2304 + (r8 + j) * 48 + c] = in ? o[j] : 0.f;
                        }
                    }
                } else {
                    int k = idx - 288;
                    int rg = k / 44, c = k - rg * 44;
                    int r0 = min(rg * 8, 36);
                    float t[12];
                    #pragma unroll
                    for (int q = 0; q < 12; ++q) t[q] = S[OFF_A + 2304 + (r0 + q) * 44 + c];
                    float ss[8];
                    float s = t[0] + t[1] + t[2] + t[3] + t[4];
                    ss[0] = s;
                    #pragma unroll
                    for (int j = 1; j < 8; ++j) { s += t[j + 4] - t[j - 1]; ss[j] = s; }
                    int gx = X0 - 6 + c;
                    float cntx = (float)(min(gx + 2, W - 1) - max(gx - 2, 0) + 1);
                    #pragma unroll
                    for (int j = 0; j < 8; ++j) {
                        int gy = Y0 - 6 + r0 + j;
                        float v = NANF;
                        if ((unsigned)gx < (unsigned)W && (unsigned)gy < (unsigned)H) {
                            float cnty = (float)(min(gy + 2, H - 1) - max(gy - 2, 0) + 1);
                            v = fabsf(__fdividef(ss[j], cntx * cnty));
                        }
                        S[OFF_GO + (r0 + j) * 44 + c] = v;
                    }
                }
            }
            __syncthreads();

            // ======== P4: h17 8-col sliding (48x32) + h7 8-col vH (44x38) ========
            for (int idx = tid; idx < 412; idx += NT) {
                if (idx < 192) {
                    int r = idx >> 2, g8 = (idx & 3) * 8;
                    #pragma unroll
                    for (int arr = 0; arr < 2; ++arr) {
                        const float* p = S + OFF_C + arr * 2304 + r * 48 + g8;
                        float t[24];
                        #pragma unroll
                        for (int q = 0; q < 6; ++q) {
                            float4 v = *(const float4*)(p + q * 4);
                            t[q*4] = v.x; t[q*4+1] = v.y; t[q*4+2] = v.z; t[q*4+3] = v.w;
                        }
                        float s = 0.f;
                        #pragma unroll
                        for (int q = 0; q < 17; ++q) s += t[q];
                        float o[8];
                        o[0] = s;
                        #pragma unroll
                        for (int j = 1; j < 8; ++j) { s += t[j + 16] - t[j - 1]; o[j] = s; }
                        float* dst = S + OFF_B + arr * 1536 + r * 32 + g8;
                        *(float4*)dst       = make_float4(o[0], o[1], o[2], o[3]);
                        *(float4*)(dst + 4) = make_float4(o[4], o[5], o[6], o[7]);
                    }
                } else {
                    int k = idx - 192;
                    int r = k / 5, g = k - r * 5;
                    int g8 = (g < 4) ? g * 8 : 30;
                    float t[14];
                    #pragma unroll
                    for (int q = 0; q < 14; ++q) t[q] = S[OFF_GO + r * 44 + g8 + q];
                    float ox[8], on[8];
                    VH7(t, ox, fmaxf);
                    VH7(t, on, fminf);
                    #pragma unroll
                    for (int j = 0; j < 8; ++j) {
                        S[OFF_A + r * 40 + g8 + j] = ox[j];
                        S[OFF_A + 1760 + r * 40 + g8 + j] = on[j];
                    }
                }
            }
            __syncthreads();

            // ======== P5: v17 (tid<256, 4-row, regs) ; m7 8-row vH (tid 256..445) ========
            if (tid < 256) {
                int rg = tid >> 5, c = tid & 31;
                int r0 = rg * 4;
                int gx = X0 + c;
                float cntx = (float)(min(gx + 8, W - 1) - max(gx - 8, 0) + 1);
                float inv[4];
                #pragma unroll
                for (int j = 0; j < 4; ++j) {
                    int gy = Y0 + r0 + j;
                    float cnty = (float)(min(gy + 8, H - 1) - max(gy - 8, 0) + 1);
                    inv[j] = __fdividef(1.f, cntx * cnty);
                }
                {
                    float t[20];
                    #pragma unroll
                    for (int q = 0; q < 20; ++q) t[q] = S[OFF_B + (r0 + q) * 32 + c];
                    float s0 = 0.f;
                    #pragma unroll
                    for (int q = 0; q < 17; ++q) s0 += t[q];
                    float s1 = s0 - t[0] + t[17];
                    float s2 = s1 - t[1] + t[18];
                    float s3 = s2 - t[2] + t[19];
                    gmv[0] = s0 * inv[0]; gmv[1] = s1 * inv[1];
                    gmv[2] = s2 * inv[2]; gmv[3] = s3 * inv[3];
                }
                {
                    float t[20];
                    #pragma unroll
                    for (int q = 0; q < 20; ++q) t[q] = S[OFF_B + 1536 + (r0 + q) * 32 + c];
                    float s0 = 0.f;
                    #pragma unroll
                    for (int q = 0; q < 17; ++q) s0 += t[q];
                    float s1 = s0 - t[0] + t[17];
                    float s2 = s1 - t[1] + t[18];
                    float s3 = s2 - t[2] + t[19];
                    gnv[0] = s0 * inv[0]; gnv[1] = s1 * inv[1];
                    gnv[2] = s2 * inv[2]; gnv[3] = s3 * inv[3];
                }
            } else if (tid < 446) {
                int k = tid - 256;                // 0..189
                int rg = k / 38, c = k - rg * 38;
                int r0 = min(rg * 8, 30);
                int gx = X0 - 3 + c;
                bool inx = (unsigned)gx < (unsigned)W;
                {
                    float t[14];
                    #pragma unroll
                    for (int q = 0; q < 14; ++q) t[q] = S[OFF_A + (r0 + q) * 40 + c];
                    float o[8];
                    VH7(t, o, fmaxf);
                    #pragma unroll
                    for (int j = 0; j < 8; ++j) {
                        int gy = Y0 - 3 + r0 + j;
                        bool in = inx && (unsigned)gy < (unsigned)H;
                        S[OFF_C + (r0 + j) * 40 + c] = in ? o[j] : 0.f;
                    }
                }
                {
                    float t[14];
                    #pragma unroll
                    for (int q = 0; q < 14; ++q) t[q] = S[OFF_A + 1760 + (r0 + q) * 40 + c];
                    float o[8];
                    VH7(t, o, fminf);
                    #pragma unroll
                    for (int j = 0; j < 8; ++j) {
                        int gy = Y0 - 3 + r0 + j;
                        bool in = inx && (unsigned)gy < (unsigned)H;
                        S[OFF_C + 1520 + (r0 + j) * 40 + c] = in ? o[j] : 0.f;
                    }
                }
            }
            __syncthreads();

            // ======== P6: h7s 8-col sliding sums (38x32) ========
            if (tid < 152) {
                int r = tid >> 2, g8 = (tid & 3) * 8;
                #pragma unroll
                for (int arr = 0; arr < 2; ++arr) {
                    const float* p = S + OFF_C + arr * 1520 + r * 40 + g8;
                    float t[16];
                    #pragma unroll
                    for (int q = 0; q < 4; ++q) {
                        float4 v = *(const float4*)(p + q * 4);
                        t[q*4] = v.x; t[q*4+1] = v.y; t[q*4+2] = v.z; t[q*4+3] = v.w;
                    }
                    float s = t[0]+t[1]+t[2]+t[3]+t[4]+t[5]+t[6];
                    float o[8];
                    o[0] = s;
                    #pragma unroll
                    for (int j = 1; j < 8; ++j) { s += t[j + 6] - t[j - 1]; o[j] = s; }
                    float* dst = S + OFF_A + arr * 1216 + r * 32 + g8;
                    *(float4*)dst       = make_float4(o[0], o[1], o[2], o[3]);
                    *(float4*)(dst + 4) = make_float4(o[4], o[5], o[6], o[7]);
                }
            }
            __syncthreads();

            // ======== P7: final (32x32), tid<256, 4-row ========
            if (tid < 256) {
                int rg = tid >> 5, c = tid & 31;
                int r0 = rg * 4;
                float sA[4], sD[4];
                {
                    float t[10];
                    #pragma unroll
                    for (int q = 0; q < 10; ++q) t[q] = S[OFF_A + (r0 + q) * 32 + c];
                    sA[0] = t[0]+t[1]+t[2]+t[3]+t[4]+t[5]+t[6];
                    sA[1] = sA[0] - t[0] + t[7];
                    sA[2] = sA[1] - t[1] + t[8];
                    sA[3] = sA[2] - t[2] + t[9];
                }
                {
                    float t[10];
                    #pragma unroll
                    for (int q = 0; q < 10; ++q) t[q] = S[OFF_A + 1216 + (r0 + q) * 32 + c];
                    sD[0] = t[0]+t[1]+t[2]+t[3]+t[4]+t[5]+t[6];
                    sD[1] = sD[0] - t[0] + t[7];
                    sD[2] = sD[1] - t[1] + t[8];
                    sD[3] = sD[2] - t[2] + t[9];
                }
                int gx = X0 + c;
                float cntx = (float)(min(gx + 3, W - 1) - max(gx - 3, 0) + 1);
                #pragma unroll
                for (int j = 0; j < 4; ++j) {
                    int gy = Y0 + r0 + j;
                    float cnty = (float)(min(gy + 3, H - 1) - max(gy - 3, 0) + 1);
                    float inv = __fdividef(1.f, cntx * cnty);
                    float pmax = sA[j] * inv, pmin = sD[j] * inv;
                    float go = S[OFF_GO + (r0 + j + 6) * 44 + c + 6];
                    float ga = S[OFF_SGA + (r0 + j + 12) * 56 + c + 12];
                    float gn = __fdividef(go - pmin, fabsf(pmax - pmin) + EPSF);
                    float gn1 = __fdividef(ga - gnv[j], fabsf(gmv[j] - gnv[j]) + EPSF);
                    float val = (gn + 0.01f) * gn1;
                    if (img == 0) {
                        vsave[dir][j] = val;
                    } else {
                        float rv = vsave[dir][j];
                        acc += (double)(rv * expf(-10.f * (rv + val)));
                    }
                }
            }
            __syncthreads();
        }
    }

    // ---- block reduction ----
    int tx = tid & 31, ty = tid >> 5;
    #pragma unroll
    for (int off = 16; off; off >>= 1) acc += __shfl_down_sync(0xffffffffu, acc, off);
    if (tx == 0) sred[ty] = acc;
    __syncthreads();
    if (ty == 0 && tx < NT / 32) {
        double w = sred[tx];
        #pragma unroll
        for (int off = (NT / 64); off; off >>= 1) w += __shfl_down_sync(0xffffffffu, w, off);
        if (tx == 0) atomicAdd(&g_acc, w);
    }
}

__global__ void k_out(float* __restrict__ out) {
    out[0] = (float)(g_acc / (double)NMAP);
}

extern "C" void kernel_launch(void* const* d_in, const int* in_sizes, int n_in,
                              void* d_out, int out_size) {
    const float* R_low = (const float*)d_in[0];
    const float* low = (const float*)d_in[1];
    float* out = (float*)d_out;

    cudaFuncSetAttribute(k_mega, cudaFuncAttributeMaxDynamicSharedMemorySize, SMEM_BYTES);

    float* grayR;
    cudaGetSymbolAddress((void**)&grayR, g_gray);
    float* grayL = grayR + NMAP;

    int gray_blocks = (NMAP / 4 + 255) / 256;

    k_zero<<<1, 1>>>();
    k_gray<<<gray_blocks, 256>>>(R_low, grayR);
    k_gray<<<gray_blocks, 256>>>(low, grayL);

    dim3 grd(16, 16, 16);
    k_mega<<<grd, NT, SMEM_BYTES>>>();

    k_out<<<1, 1>>>(out);
}

// round 10
// speedup vs baseline: 1.5778x; 1.2440x over previous
#include <cuda_runtime.h>
#include <math.h>

#define W 512
#define H 512
#define BATCH 16
#define NPIX (W*H)
#define NMAP (BATCH*NPIX)
#define EPSF 1e-4f
#define NT 512

#define NANF __int_as_float(0x7fffffff)

__device__ float g_gray[2 * NMAP];
__device__ double g_acc;

// ---- smem layout (floats) ----
// gray 58x58 s60 @0 (3480) ; sga 56x56 s56 @3480 (3136) ; go 44x44 s44 @6616 (1936)
// A @8552 (3520): hs5/vs5 (2112) -> h7x/h7n (2x1760) -> h7s (2x1216)
// B @12072 (5376): hm (2x2688) -> h17 (2x1536)
// C @17448 (4608): pm (2x2304) -> m7 (2x1520)
#define OFF_GRAY 0
#define OFF_SGA  3480
#define OFF_GO   6616
#define OFF_A    8552
#define OFF_B    12072
#define OFF_C    17448
#define SMEM_FLOATS 22056
#define SMEM_BYTES (SMEM_FLOATS * 4)

__global__ void k_zero() { g_acc = 0.0; }

__global__ void k_gray(const float* __restrict__ in, float* __restrict__ outp) {
    int i = blockIdx.x * blockDim.x + threadIdx.x;
    if (i >= NMAP / 4) return;
    int b = i / (NPIX / 4);
    int p = i - b * (NPIX / 4);
    const float4* base = (const float4*)(in + (size_t)b * 3 * NPIX);
    float4 r = base[p];
    float4 g = base[NPIX / 4 + p];
    float4 bl = base[2 * (NPIX / 4) + p];
    float4 o;
    o.x = 0.299f * r.x + 0.587f * g.x + 0.114f * bl.x;
    o.y = 0.299f * r.y + 0.587f * g.y + 0.114f * bl.y;
    o.z = 0.299f * r.z + 0.587f * g.z + 0.114f * bl.z;
    o.w = 0.299f * r.w + 0.587f * g.w + 0.114f * bl.w;
    ((float4*)outp)[i] = o;
}

template<int DIR, bool BORDER>
__device__ __forceinline__ void pipe(float* S, int X0, int Y0, int tid,
                                     int mode, float* vsave, double& acc)
{
    float gmv[4], gnv[4];

    // ======== P1: sga (56x56) |grad|, NaN outside (border only) ========
    #pragma unroll
    for (int idx = tid; idx < 784; idx += NT) {
        int r = idx / 14, g4 = (idx - r * 14) * 4;
        const float* p = S + OFF_GRAY + r * 60 + g4;
        float4 a = *(const float4*)p;
        float n0, n1, n2, n3;
        if (DIR == 0) {
            float e = p[4];
            n0 = a.y; n1 = a.z; n2 = a.w; n3 = e;
        } else {
            float4 bb = *(const float4*)(p + 60);
            n0 = bb.x; n1 = bb.y; n2 = bb.z; n3 = bb.w;
        }
        float4 o;
        o.x = fabsf(a.x - n0); o.y = fabsf(a.y - n1);
        o.z = fabsf(a.z - n2); o.w = fabsf(a.w - n3);
        if (BORDER) {
            int gy = Y0 - 12 + r, gxb = X0 - 12 + g4;
            bool iny = (unsigned)gy < (unsigned)H;
            if (!(iny && (unsigned)(gxb + 0) < (unsigned)W)) o.x = NANF;
            if (!(iny && (unsigned)(gxb + 1) < (unsigned)W)) o.y = NANF;
            if (!(iny && (unsigned)(gxb + 2) < (unsigned)W)) o.z = NANF;
            if (!(iny && (unsigned)(gxb + 3) < (unsigned)W)) o.w = NANF;
        }
        *(float4*)(S + OFF_SGA + r * 56 + g4) = o;
    }
    __syncthreads();

    // ======== P2: hm (56x48) + telescoped hs5/vs5 ========
    #pragma unroll
    for (int idx = tid; idx < 1200; idx += NT) {
        if (idx < 672) {
            int r = idx / 12, g4 = (idx - r * 12) * 4;
            const float* p = S + OFF_SGA + r * 56 + g4;
            float4 A = *(const float4*)p;
            float4 Bv = *(const float4*)(p + 4);
            float4 Cv = *(const float4*)(p + 8);
            float t0=A.x,t1=A.y,t2=A.z,t3=A.w,t4=Bv.x,t5=Bv.y,t6=Bv.z,t7=Bv.w,t8=Cv.x,t9=Cv.y,t10=Cv.z,t11=Cv.w;
            float cx = fmaxf(fmaxf(fmaxf(t3,t4),fmaxf(t5,t6)),fmaxf(t7,t8));
            float cn = fminf(fminf(fminf(t3,t4),fminf(t5,t6)),fminf(t7,t8));
            float4 ox, on;
            ox.x = fmaxf(fmaxf(fmaxf(cx,t0),t1),t2);
            ox.y = fmaxf(fmaxf(fmaxf(cx,t1),t2),t9);
            ox.z = fmaxf(fmaxf(fmaxf(cx,t2),t9),t10);
            ox.w = fmaxf(fmaxf(fmaxf(cx,t9),t10),t11);
            on.x = fminf(fminf(fminf(cn,t0),t1),t2);
            on.y = fminf(fminf(fminf(cn,t1),t2),t9);
            on.z = fminf(fminf(fminf(cn,t2),t9),t10);
            on.w = fminf(fminf(fminf(cn,t9),t10),t11);
            *(float4*)(S + OFF_B + r * 48 + g4) = ox;
            *(float4*)(S + OFF_B + 2688 + r * 48 + g4) = on;
        } else {
            int k = idx - 672;    // 528 items
            if (DIR == 0) {
                // hs5: 48 rows x 44 cols (stride 44). hs5 = gray[gx-2] - gray[gx+3] (clamped/zero-pad)
                int r = k / 11, c4 = (k - r * 11) * 4;
                float4 o;
                if (!BORDER) {
                    const float* p = S + OFF_GRAY + (r + 4) * 60 + c4;
                    float4 A = *(const float4*)(p + 4);
                    float4 Bv = *(const float4*)(p + 8);
                    float e = p[12];
                    o = make_float4(A.x - Bv.y, A.y - Bv.z, A.z - Bv.w, A.w - e);
                } else {
                    float v[4];
                    #pragma unroll
                    for (int j = 0; j < 4; ++j) {
                        int acol = c4 + 4 + j;
                        if (X0 == 0) acol = max(acol, 12);   // clamp gx-2 to 0 at left edge
                        float av = S[OFF_GRAY + (r + 4) * 60 + acol];
                        float bv = S[OFF_GRAY + (r + 4) * 60 + c4 + 9 + j];
                        v[j] = av - bv;
                    }
                    o = make_float4(v[0], v[1], v[2], v[3]);
                }
                *(float4*)(S + OFF_A + r * 44 + c4) = o;
            } else {
                // vs5: 44 rows x 48 cols (stride 48). vs5 = gray[gy-2] - gray[gy+3]
                int r = k / 12, c4 = (k - r * 12) * 4;
                int arow = r + 4;
                if (BORDER && Y0 == 0) arow = max(arow, 12);
                float4 T = *(const float4*)(S + OFF_GRAY + arow * 60 + c4 + 4);
                float4 Bo = *(const float4*)(S + OFF_GRAY + (r + 9) * 60 + c4 + 4);
                *(float4*)(S + OFF_A + r * 48 + c4) =
                    make_float4(T.x - Bo.x, T.y - Bo.y, T.z - Bo.z, T.w - Bo.w);
            }
        }
    }
    __syncthreads();

    // ======== P3: pm (48x48, masked 0 outside) + go (44x44) ========
    #pragma unroll
    for (int idx = tid; idx < 1060; idx += NT) {
        if (idx < 576) {
            int rg = idx / 48, c = idx - rg * 48;
            int r4 = rg * 4;
            {
                float t[12];
                #pragma unroll
                for (int q = 0; q < 12; ++q) t[q] = S[OFF_B + (r4 + q) * 48 + c];
                float cx = fmaxf(fmaxf(fmaxf(t[3],t[4]),fmaxf(t[5],t[6])),fmaxf(t[7],t[8]));
                float o0 = fmaxf(fmaxf(fmaxf(cx,t[0]),t[1]),t[2]);
                float o1 = fmaxf(fmaxf(fmaxf(cx,t[1]),t[2]),t[9]);
                float o2 = fmaxf(fmaxf(fmaxf(cx,t[2]),t[9]),t[10]);
                float o3 = fmaxf(fmaxf(fmaxf(cx,t[9]),t[10]),t[11]);
                if (BORDER) {
                    int gx = X0 - 8 + c;
                    bool inx = (unsigned)gx < (unsigned)W;
                    int gyb = Y0 - 8 + r4;
                    if (!(inx && (unsigned)(gyb+0)<(unsigned)H)) o0 = 0.f;
                    if (!(inx && (unsigned)(gyb+1)<(unsigned)H)) o1 = 0.f;
                    if (!(inx && (unsigned)(gyb+2)<(unsigned)H)) o2 = 0.f;
                    if (!(inx && (unsigned)(gyb+3)<(unsigned)H)) o3 = 0.f;
                }
                S[OFF_C + (r4 + 0) * 48 + c] = o0;
                S[OFF_C + (r4 + 1) * 48 + c] = o1;
                S[OFF_C + (r4 + 2) * 48 + c] = o2;
                S[OFF_C + (r4 + 3) * 48 + c] = o3;
            }
            {
                float t[12];
                #pragma unroll
                for (int q = 0; q < 12; ++q) t[q] = S[OFF_B + 2688 + (r4 + q) * 48 + c];
                float cn = fminf(fminf(fminf(t[3],t[4]),fminf(t[5],t[6])),fminf(t[7],t[8]));
                float o0 = fminf(fminf(fminf(cn,t[0]),t[1]),t[2]);
                float o1 = fminf(fminf(fminf(cn,t[1]),t[2]),t[9]);
                float o2 = fminf(fminf(fminf(cn,t[2]),t[9]),t[10]);
                float o3 = fminf(fminf(fminf(cn,t[9]),t[10]),t[11]);
                if (BORDER) {
                    int gx = X0 - 8 + c;
                    bool inx = (unsigned)gx < (unsigned)W;
                    int gyb = Y0 - 8 + r4;
                    if (!(inx && (unsigned)(gyb+0)<(unsigned)H)) o0 = 0.f;
                    if (!(inx && (unsigned)(gyb+1)<(unsigned)H)) o1 = 0.f;
                    if (!(inx && (unsigned)(gyb+2)<(unsigned)H)) o2 = 0.f;
                    if (!(inx && (unsigned)(gyb+3)<(unsigned)H)) o3 = 0.f;
                }
                S[OFF_C + 2304 + (r4 + 0) * 48 + c] = o0;
                S[OFF_C + 2304 + (r4 + 1) * 48 + c] = o1;
                S[OFF_C + 2304 + (r4 + 2) * 48 + c] = o2;
                S[OFF_C + 2304 + (r4 + 3) * 48 + c] = o3;
            }
        } else {
            int k = idx - 576;    // 484 items -> go
            if (DIR == 0) {
                int rg = k / 44, c = k - rg * 44;
                int r4 = rg * 4;
                float t[8];
                #pragma unroll
                for (int q = 0; q < 8; ++q) t[q] = S[OFF_A + (r4 + q) * 44 + c];
                float s0 = t[0] + t[1] + t[2] + t[3] + t[4];
                float s1 = s0 - t[0] + t[5];
                float s2 = s1 - t[1] + t[6];
                float s3 = s2 - t[2] + t[7];
                float ss[4] = { s0, s1, s2, s3 };
                #pragma unroll
                for (int j = 0; j < 4; ++j) {
                    float v;
                    if (!BORDER) {
                        v = fabsf(ss[j] * 0.04f);
                    } else {
                        int gx = X0 - 6 + c, gy = Y0 - 6 + r4 + j;
                        if ((unsigned)gx < (unsigned)W && (unsigned)gy < (unsigned)H) {
                            float cntx = (float)(min(gx + 2, W - 1) - max(gx - 2, 0) + 1);
                            float cnty = (float)(min(gy + 2, H - 1) - max(gy - 2, 0) + 1);
                            v = fabsf(__fdividef(ss[j], cntx * cnty));
                        } else v = NANF;
                    }
                    S[OFF_GO + (r4 + j) * 44 + c] = v;
                }
            } else {
                int r = k / 11, c4 = (k - r * 11) * 4;
                float4 A = *(const float4*)(S + OFF_A + r * 48 + c4);
                float4 Bv = *(const float4*)(S + OFF_A + r * 48 + c4 + 4);
                float t0=A.x,t1=A.y,t2=A.z,t3=A.w,t4=Bv.x,t5=Bv.y,t6=Bv.z,t7=Bv.w;
                float s0 = t0 + t1 + t2 + t3 + t4;
                float s1 = s0 - t0 + t5;
                float s2 = s1 - t1 + t6;
                float s3 = s2 - t2 + t7;
                float ss[4] = { s0, s1, s2, s3 };
                float4 o;
                float* op = &o.x;
                #pragma unroll
                for (int j = 0; j < 4; ++j) {
                    float v;
                    if (!BORDER) {
                        v = fabsf(ss[j] * 0.04f);
                    } else {
                        int gx = X0 - 6 + c4 + j, gy = Y0 - 6 + r;
                        if ((unsigned)gx < (unsigned)W && (unsigned)gy < (unsigned)H) {
                            float cntx = (float)(min(gx + 2, W - 1) - max(gx - 2, 0) + 1);
                            float cnty = (float)(min(gy + 2, H - 1) - max(gy - 2, 0) + 1);
                            v = fabsf(__fdividef(ss[j], cntx * cnty));
                        } else v = NANF;
                    }
                    op[j] = v;
                }
                *(float4*)(S + OFF_GO + r * 44 + c4) = o;
            }
        }
    }
    __syncthreads();

    // ======== P4: h17 (48x32) + h7 (44x38) ========
    #pragma unroll
    for (int idx = tid; idx < 824; idx += NT) {
        if (idx < 384) {
            int r = idx / 8, g4 = (idx & 7) * 4;
            #pragma unroll
            for (int arr = 0; arr < 2; ++arr) {
                const float* p = S + OFF_C + arr * 2304 + r * 48 + g4;
                float t[20];
                #pragma unroll
                for (int q = 0; q < 5; ++q) {
                    float4 v = *(const float4*)(p + q * 4);
                    t[q*4] = v.x; t[q*4+1] = v.y; t[q*4+2] = v.z; t[q*4+3] = v.w;
                }
                float s0 = 0.f;
                #pragma unroll
                for (int q = 0; q < 17; ++q) s0 += t[q];
                float s1 = s0 - t[0] + t[17];
                float s2 = s1 - t[1] + t[18];
                float s3 = s2 - t[2] + t[19];
                *(float4*)(S + OFF_B + arr * 1536 + r * 32 + g4) = make_float4(s0, s1, s2, s3);
            }
        } else {
            int k = idx - 384;     // 440 items
            int r = k / 10, g = k - r * 10;
            if (g < 9) {
                int g4 = g * 4;
                const float* p = S + OFF_GO + r * 44 + g4;
                float4 A = *(const float4*)p;
                float4 Bv = *(const float4*)(p + 4);
                float4 Cv = *(const float4*)(p + 8);
                float t0=A.x,t1=A.y,t2=A.z,t3=A.w,t4=Bv.x,t5=Bv.y,t6=Bv.z,t7=Bv.w,t8=Cv.x,t9=Cv.y;
                float cx = fmaxf(fmaxf(t3,t4),fmaxf(t5,t6));
                float cn = fminf(fminf(t3,t4),fminf(t5,t6));
                float4 ox, on;
                ox.x = fmaxf(fmaxf(fmaxf(cx,t0),t1),t2);
                ox.y = fmaxf(fmaxf(fmaxf(cx,t1),t2),t7);
                ox.z = fmaxf(fmaxf(fmaxf(cx,t2),t7),t8);
                ox.w = fmaxf(fmaxf(fmaxf(cx,t7),t8),t9);
                on.x = fminf(fminf(fminf(cn,t0),t1),t2);
                on.y = fminf(fminf(fminf(cn,t1),t2),t7);
                on.z = fminf(fminf(fminf(cn,t2),t7),t8);
                on.w = fminf(fminf(fminf(cn,t7),t8),t9);
                *(float4*)(S + OFF_A + r * 40 + g4) = ox;
                *(float4*)(S + OFF_A + 1760 + r * 40 + g4) = on;
            } else {
                const float* p = S + OFF_GO + r * 44 + 36;
                float4 A = *(const float4*)p;
                float4 Bv = *(const float4*)(p + 4);
                float t0=A.x,t1=A.y,t2=A.z,t3=A.w,t4=Bv.x,t5=Bv.y,t6=Bv.z,t7=Bv.w;
                float c6x = fmaxf(fmaxf(t1,t2),fmaxf(fmaxf(t3,t4),fmaxf(t5,t6)));
                float c6n = fminf(fminf(t1,t2),fminf(fminf(t3,t4),fminf(t5,t6)));
                S[OFF_A + r * 40 + 36] = fmaxf(c6x, t0);
                S[OFF_A + r * 40 + 37] = fmaxf(c6x, t7);
                S[OFF_A + 1760 + r * 40 + 36] = fminf(c6n, t0);
                S[OFF_A + 1760 + r * 40 + 37] = fminf(c6n, t7);
            }
        }
    }
    __syncthreads();

    // ======== P5: m7 (38x38, masked) ; v17 -> registers ========
    #pragma unroll
    for (int idx = tid; idx < 380; idx += NT) {
        int rg = idx / 38, c = idx - rg * 38;
        int r0 = min(rg * 4, 34);
        #pragma unroll
        for (int arr = 0; arr < 2; ++arr) {
            float t[10];
            #pragma unroll
            for (int q = 0; q < 10; ++q) t[q] = S[OFF_A + arr * 1760 + (r0 + q) * 40 + c];
            float o0, o1, o2, o3;
            if (arr == 0) {
                float cx = fmaxf(fmaxf(t[3],t[4]),fmaxf(t[5],t[6]));
                o0 = fmaxf(fmaxf(fmaxf(cx,t[0]),t[1]),t[2]);
                o1 = fmaxf(fmaxf(fmaxf(cx,t[1]),t[2]),t[7]);
                o2 = fmaxf(fmaxf(fmaxf(cx,t[2]),t[7]),t[8]);
                o3 = fmaxf(fmaxf(fmaxf(cx,t[7]),t[8]),t[9]);
            } else {
                float cn = fminf(fminf(t[3],t[4]),fminf(t[5],t[6]));
                o0 = fminf(fminf(fminf(cn,t[0]),t[1]),t[2]);
                o1 = fminf(fminf(fminf(cn,t[1]),t[2]),t[7]);
                o2 = fminf(fminf(fminf(cn,t[2]),t[7]),t[8]);
                o3 = fminf(fminf(fminf(cn,t[7]),t[8]),t[9]);
            }
            if (BORDER) {
                int gx = X0 - 3 + c;
                bool inx = (unsigned)gx < (unsigned)W;
                int gyb = Y0 - 3 + r0;
                if (!(inx && (unsigned)(gyb+0)<(unsigned)H)) o0 = 0.f;
                if (!(inx && (unsigned)(gyb+1)<(unsigned)H)) o1 = 0.f;
                if (!(inx && (unsigned)(gyb+2)<(unsigned)H)) o2 = 0.f;
                if (!(inx && (unsigned)(gyb+3)<(unsigned)H)) o3 = 0.f;
            }
            S[OFF_C + arr * 1520 + (r0 + 0) * 40 + c] = o0;
            S[OFF_C + arr * 1520 + (r0 + 1) * 40 + c] = o1;
            S[OFF_C + arr * 1520 + (r0 + 2) * 40 + c] = o2;
            S[OFF_C + arr * 1520 + (r0 + 3) * 40 + c] = o3;
        }
    }
    if (tid < 256) {
        int rg = tid >> 5, c = tid & 31;
        int r0 = rg * 4;
        float inv[4];
        if (!BORDER) {
            #pragma unroll
            for (int j = 0; j < 4; ++j) inv[j] = 1.f / 289.f;
        } else {
            int gx = X0 + c;
            float cntx = (float)(min(gx + 8, W - 1) - max(gx - 8, 0) + 1);
            #pragma unroll
            for (int j = 0; j < 4; ++j) {
                int gy = Y0 + r0 + j;
                float cnty = (float)(min(gy + 8, H - 1) - max(gy - 8, 0) + 1);
                inv[j] = __fdividef(1.f, cntx * cnty);
            }
        }
        {
            float t[20];
            #pragma unroll
            for (int q = 0; q < 20; ++q) t[q] = S[OFF_B + (r0 + q) * 32 + c];
            float s0 = 0.f;
            #pragma unroll
            for (int q = 0; q < 17; ++q) s0 += t[q];
            float s1 = s0 - t[0] + t[17];
            float s2 = s1 - t[1] + t[18];
            float s3 = s2 - t[2] + t[19];
            gmv[0] = s0 * inv[0]; gmv[1] = s1 * inv[1];
            gmv[2] = s2 * inv[2]; gmv[3] = s3 * inv[3];
        }
        {
            float t[20];
            #pragma unroll
            for (int q = 0; q < 20; ++q) t[q] = S[OFF_B + 1536 + (r0 + q) * 32 + c];
            float s0 = 0.f;
            #pragma unroll
            for (int q = 0; q < 17; ++q) s0 += t[q];
            float s1 = s0 - t[0] + t[17];
            float s2 = s1 - t[1] + t[18];
            float s3 = s2 - t[2] + t[19];
            gnv[0] = s0 * inv[0]; gnv[1] = s1 * inv[1];
            gnv[2] = s2 * inv[2]; gnv[3] = s3 * inv[3];
        }
    }
    __syncthreads();

    // ======== P6: h7s (38x32) ========
    #pragma unroll
    for (int idx = tid; idx < 304; idx += NT) {
        int r = idx / 8, g4 = (idx & 7) * 4;
        #pragma unroll
        for (int arr = 0; arr < 2; ++arr) {
            const float* p = S + OFF_C + arr * 1520 + r * 40 + g4;
            float4 A = *(const float4*)p;
            float4 Bv = *(const float4*)(p + 4);
            float4 Cv = *(const float4*)(p + 8);
            float t0=A.x,t1=A.y,t2=A.z,t3=A.w,t4=Bv.x,t5=Bv.y,t6=Bv.z,t7=Bv.w,t8=Cv.x,t9=Cv.y;
            float s0 = t0+t1+t2+t3+t4+t5+t6;
            float s1 = s0 - t0 + t7;
            float s2 = s1 - t1 + t8;
            float s3 = s2 - t2 + t9;
            *(float4*)(S + OFF_A + arr * 1216 + r * 32 + g4) = make_float4(s0, s1, s2, s3);
        }
    }
    __syncthreads();

    // ======== P7: final (32x32) ========
    if (tid < 256) {
        int rg = tid >> 5, c = tid & 31;
        int r0 = rg * 4;
        float sA[4], sD[4];
        {
            float t[10];
            #pragma unroll
            for (int q = 0; q < 10; ++q) t[q] = S[OFF_A + (r0 + q) * 32 + c];
            sA[0] = t[0]+t[1]+t[2]+t[3]+t[4]+t[5]+t[6];
            sA[1] = sA[0] - t[0] + t[7];
            sA[2] = sA[1] - t[1] + t[8];
            sA[3] = sA[2] - t[2] + t[9];
        }
        {
            float t[10];
            #pragma unroll
            for (int q = 0; q < 10; ++q) t[q] = S[OFF_A + 1216 + (r0 + q) * 32 + c];
            sD[0] = t[0]+t[1]+t[2]+t[3]+t[4]+t[5]+t[6];
            sD[1] = sD[0] - t[0] + t[7];
            sD[2] = sD[1] - t[1] + t[8];
            sD[3] = sD[2] - t[2] + t[9];
        }
        #pragma unroll
        for (int j = 0; j < 4; ++j) {
            float inv;
            if (!BORDER) {
                inv = 1.f / 49.f;
            } else {
                int gx = X0 + c, gy = Y0 + r0 + j;
                float cntx = (float)(min(gx + 3, W - 1) - max(gx - 3, 0) + 1);
                float cnty = (float)(min(gy + 3, H - 1) - max(gy - 3, 0) + 1);
                inv = __fdividef(1.f, cntx * cnty);
            }
            float pmax = sA[j] * inv, pmin = sD[j] * inv;
            float go = S[OFF_GO + (r0 + j + 6) * 44 + c + 6];
            float ga = S[OFF_SGA + (r0 + j + 12) * 56 + c + 12];
            float gn = __fdividef(go - pmin, fabsf(pmax - pmin) + EPSF);
            float gn1 = __fdividef(ga - gnv[j], fabsf(gmv[j] - gnv[j]) + EPSF);
            float val = (gn + 0.01f) * gn1;
            if (mode == 0) {
                vsave[j] = val;
            } else {
                float rv = vsave[j];
                acc += (double)(rv * expf(-10.f * (rv + val)));
            }
        }
    }
    __syncthreads();
}

template<bool BORDER>
__device__ __forceinline__ void run(float* S, int X0, int Y0, int b, int tid, double& acc)
{
    float vsx[4], vsy[4];
    #pragma unroll
    for (int img = 0; img < 2; ++img) {
        const float* __restrict__ gp = g_gray + (size_t)img * NMAP + (size_t)b * NPIX;
        if (!BORDER) {
            #pragma unroll
            for (int idx = tid; idx < 870; idx += NT) {
                int r = idx / 15, c4 = (idx - r * 15) * 4;
                float4 v = *(const float4*)(gp + (Y0 - 12 + r) * W + X0 - 12 + c4);
                *(float4*)(S + OFF_GRAY + r * 60 + c4) = v;
            }
        } else {
            for (int idx = tid; idx < 3364; idx += NT) {
                int r = idx / 58, c = idx - r * 58;
                int gy = Y0 - 12 + r, gx = X0 - 12 + c;
                float v = 0.f;
                if ((unsigned)gx < (unsigned)W && (unsigned)gy < (unsigned)H)
                    v = __ldg(gp + gy * W + gx);
                S[OFF_GRAY + r * 60 + c] = v;
            }
        }
        __syncthreads();
        pipe<0, BORDER>(S, X0, Y0, tid, img, vsx, acc);
        pipe<1, BORDER>(S, X0, Y0, tid, img, vsy, acc);
    }
}

__global__ __launch_bounds__(NT, 2)
void k_mega() {
    extern __shared__ float S[];
    __shared__ double sred[NT / 32];

    const int b = blockIdx.z;
    const int X0 = blockIdx.x * 32, Y0 = blockIdx.y * 32;
    const int tid = threadIdx.x;

    double acc = 0.0;
    bool border = (blockIdx.x == 0) | (blockIdx.x == 15) | (blockIdx.y == 0) | (blockIdx.y == 15);
    if (border) run<true>(S, X0, Y0, b, tid, acc);
    else        run<false>(S, X0, Y0, b, tid, acc);

    int tx = tid & 31, ty = tid >> 5;
    #pragma unroll
    for (int off = 16; off; off >>= 1) acc += __shfl_down_sync(0xffffffffu, acc, off);
    if (tx == 0) sred[ty] = acc;
    __syncthreads();
    if (ty == 0 && tx < NT / 32) {
        double w = sred[tx];
        #pragma unroll
        for (int off = (NT / 64); off; off >>= 1) w += __shfl_down_sync(0xffffffffu, w, off);
        if (tx == 0) atomicAdd(&g_acc, w);
    }
}

__global__ void k_out(float* __restrict__ out) {
    out[0] = (float)(g_acc / (double)NMAP);
}

extern "C" void kernel_launch(void* const* d_in, const int* in_sizes, int n_in,
                              void* d_out, int out_size) {
    const float* R_low = (const float*)d_in[0];
    const float* low = (const float*)d_in[1];
    float* out = (float*)d_out;

    cudaFuncSetAttribute(k_mega, cudaFuncAttributeMaxDynamicSharedMemorySize, SMEM_BYTES);

    float* grayR;
    cudaGetSymbolAddress((void**)&grayR, g_gray);
    float* grayL = grayR + NMAP;

    int gray_blocks = (NMAP / 4 + 255) / 256;

    k_zero<<<1, 1>>>();
    k_gray<<<gray_blocks, 256>>>(R_low, grayR);
    k_gray<<<gray_blocks, 256>>>(low, grayL);

    dim3 grd(16, 16, 16);
    k_mega<<<grd, NT, SMEM_BYTES>>>();

    k_out<<<1, 1>>>(out);
}